// round 6
// baseline (speedup 1.0000x reference)
#include <cuda_runtime.h>
#include <cuda_bf16.h>
#include <math.h>
#include <stdint.h>

// ---------------- Problem constants (fixed shapes) ----------------
#define SEQ       65536
#define EMBED     1280
#define NECK      320
#define QKVD      960      // 3 * NECK
#define NHEAD     4
#define HDIM      80
#define S1C       256
#define TC        256

// ---------------- Scratch (alloc-free: __device__ globals) --------
__device__ float g_qkv[(size_t)SEQ * QKVD];     // [t*S1+s, 960]
__device__ float g_att[(size_t)SEQ * NECK];     // [s*T+t, 320] (tf32)
__device__ float g_hid[(size_t)SEQ * EMBED];    // tf32 hidden
__device__ float g_wqkv[(size_t)QKVD * EMBED];  // tf32 w_qkv
__device__ float g_wproj[(size_t)EMBED * NECK]; // tf32 w_proj

// ================= helpers ========================================
__device__ __forceinline__ float to_tf32(float x) {
    uint32_t u;
    asm("cvt.rna.tf32.f32 %0, %1;" : "=r"(u) : "f"(x));
    return __uint_as_float(u);
}

__device__ __forceinline__ void mma_tf32(float4& d,
    float a0, float a1, float a2, float a3, float b0, float b1)
{
    asm volatile(
        "mma.sync.aligned.m16n8k8.row.col.f32.tf32.tf32.f32 "
        "{%0,%1,%2,%3}, {%4,%5,%6,%7}, {%8,%9}, {%0,%1,%2,%3};\n"
        : "+f"(d.x), "+f"(d.y), "+f"(d.z), "+f"(d.w)
        : "r"(__float_as_uint(a0)), "r"(__float_as_uint(a1)),
          "r"(__float_as_uint(a2)), "r"(__float_as_uint(a3)),
          "r"(__float_as_uint(b0)), "r"(__float_as_uint(b1)));
}

// ================= TF32 tensor-core GEMM ==========================
// C[M,N] = A[M,K] @ B[N,K]^T + bias[N]; A,B already tf32-rounded.
// Block 128x128, BK=16, 256 threads (8 warps), warp tile 64x32.
// 2 CTAs/SM (low regs) to overlap syncs/prologue/epilogue.
// Smem per tile row r (16 k): phys(r,k)=r*16+4*((k&3)^(r&3))+(k>>2)

__global__ __launch_bounds__(256, 2)
void gemm_tf32_tn_bias(const float* __restrict__ A,
                       const float* __restrict__ B,
                       const float* __restrict__ bias,
                       float* __restrict__ C,
                       int M, int N, int K)
{
    __shared__ float As[2][128 * 16];
    __shared__ float Bs[2][128 * 16];

    const int tid  = threadIdx.x;
    const int lane = tid & 31;
    const int warp = tid >> 5;
    const int wm   = warp >> 2;      // 0..1 (64 M-rows)
    const int wn   = warp & 3;       // 0..3 (32 N-cols)
    const int g    = lane >> 2;
    const int t4   = lane & 3;
    const int sw   = ((t4 ^ (g & 3)) << 2);

    const int bm = blockIdx.y * 128;
    const int bn = blockIdx.x * 128;

    const int r2 = tid >> 1;         // 0..127 load row
    const int jc = tid & 1;          // 2 float4 cols per row half? no:
    // each row of 16 floats = 4 float4; 256 threads, 128 rows -> 2 thr/row,
    // each thread stores 2 float4 (cols jc*2, jc*2+1)

    float4 ra[2], rb[2];
    float4 acc[4][4];
    #pragma unroll
    for (int i = 0; i < 4; i++)
        #pragma unroll
        for (int j = 0; j < 4; j++)
            acc[i][j] = make_float4(0.f, 0.f, 0.f, 0.f);

    const int KT = K >> 4;

    // -------- prologue --------
    {
        const float* pA = A + (size_t)(bm + r2) * K + 8 * jc;
        ra[0] = *(const float4*)(pA);
        ra[1] = *(const float4*)(pA + 4);
        if (bn + r2 < N) {
            const float* pB = B + (size_t)(bn + r2) * K + 8 * jc;
            rb[0] = *(const float4*)(pB);
            rb[1] = *(const float4*)(pB + 4);
        } else {
            rb[0] = rb[1] = make_float4(0.f, 0.f, 0.f, 0.f);
        }
    }
    #pragma unroll
    for (int i = 0; i < 2; i++) {
        const int c = 2 * jc + i;          // float4 column 0..3
        float* pa = &As[0][r2 * 16];
        float* pb = &Bs[0][r2 * 16];
        pa[((0 ^ (r2 & 3)) << 2) + c] = ra[i].x;
        pa[((1 ^ (r2 & 3)) << 2) + c] = ra[i].y;
        pa[((2 ^ (r2 & 3)) << 2) + c] = ra[i].z;
        pa[((3 ^ (r2 & 3)) << 2) + c] = ra[i].w;
        pb[((0 ^ (r2 & 3)) << 2) + c] = rb[i].x;
        pb[((1 ^ (r2 & 3)) << 2) + c] = rb[i].y;
        pb[((2 ^ (r2 & 3)) << 2) + c] = rb[i].z;
        pb[((3 ^ (r2 & 3)) << 2) + c] = rb[i].w;
    }
    __syncthreads();

    // -------- mainloop --------
    for (int kt = 0; kt < KT; kt++) {
        const int buf = kt & 1;

        if (kt + 1 < KT) {
            const int k0 = (kt + 1) << 4;
            const float* pA = A + (size_t)(bm + r2) * K + k0 + 8 * jc;
            ra[0] = *(const float4*)(pA);
            ra[1] = *(const float4*)(pA + 4);
            if (bn + r2 < N) {
                const float* pB = B + (size_t)(bn + r2) * K + k0 + 8 * jc;
                rb[0] = *(const float4*)(pB);
                rb[1] = *(const float4*)(pB + 4);
            } else {
                rb[0] = rb[1] = make_float4(0.f, 0.f, 0.f, 0.f);
            }
        }

        const float* pa = &As[buf][(wm * 64 + g) * 16 + sw];
        const float* pb = &Bs[buf][(wn * 32 + g) * 16 + sw];

        float4 fb[4];
        #pragma unroll
        for (int nt = 0; nt < 4; nt++)
            fb[nt] = *(const float4*)(pb + nt * 128);

        #pragma unroll
        for (int mt = 0; mt < 4; mt++) {
            const float4 fa  = *(const float4*)(pa + mt * 256);
            const float4 fa2 = *(const float4*)(pa + mt * 256 + 128);
            #pragma unroll
            for (int nt = 0; nt < 4; nt++) {
                mma_tf32(acc[mt][nt], fa.x, fa2.x, fa.y, fa2.y, fb[nt].x, fb[nt].y);
                mma_tf32(acc[mt][nt], fa.z, fa2.z, fa.w, fa2.w, fb[nt].z, fb[nt].w);
            }
        }

        if (kt + 1 < KT) {
            const int nb = buf ^ 1;
            #pragma unroll
            for (int i = 0; i < 2; i++) {
                const int c = 2 * jc + i;
                float* qa = &As[nb][r2 * 16];
                float* qb = &Bs[nb][r2 * 16];
                qa[((0 ^ (r2 & 3)) << 2) + c] = ra[i].x;
                qa[((1 ^ (r2 & 3)) << 2) + c] = ra[i].y;
                qa[((2 ^ (r2 & 3)) << 2) + c] = ra[i].z;
                qa[((3 ^ (r2 & 3)) << 2) + c] = ra[i].w;
                qb[((0 ^ (r2 & 3)) << 2) + c] = rb[i].x;
                qb[((1 ^ (r2 & 3)) << 2) + c] = rb[i].y;
                qb[((2 ^ (r2 & 3)) << 2) + c] = rb[i].z;
                qb[((3 ^ (r2 & 3)) << 2) + c] = rb[i].w;
            }
            __syncthreads();
        }
    }

    // -------- epilogue: bias + store --------
    #pragma unroll
    for (int mt = 0; mt < 4; mt++) {
        const int row = bm + wm * 64 + mt * 16 + g;
        #pragma unroll
        for (int nt = 0; nt < 4; nt++) {
            const int col = bn + wn * 32 + nt * 8 + 2 * t4;
            if (col < N) {
                const float bx = __ldg(bias + col), by = __ldg(bias + col + 1);
                float2 v0 = make_float2(acc[mt][nt].x + bx, acc[mt][nt].y + by);
                float2 v1 = make_float2(acc[mt][nt].z + bx, acc[mt][nt].w + by);
                *(float2*)(C + (size_t)row * N + col)       = v0;
                *(float2*)(C + (size_t)(row + 8) * N + col) = v1;
            }
        }
    }
}

// ---------------- tf32 pre-rounding kernel (single launch) --------
// layout: [0, n4h) hid, [n4h, n4h+n4q) wqkv, then wproj
__global__ void cvt_all_kernel(const float4* __restrict__ hid_in,
                               const float4* __restrict__ wqkv_in,
                               const float4* __restrict__ wproj_in,
                               float4* __restrict__ hid_out,
                               float4* __restrict__ wqkv_out,
                               float4* __restrict__ wproj_out)
{
    const int n4h = (SEQ * EMBED) / 4;
    const int n4q = (QKVD * EMBED) / 4;
    const int n4p = (EMBED * NECK) / 4;
    int i = blockIdx.x * blockDim.x + threadIdx.x;
    const float4* in;
    float4* out;
    if (i < n4h)            { in = hid_in + i;                 out = hid_out + i; }
    else if (i < n4h + n4q) { in = wqkv_in + (i - n4h);        out = wqkv_out + (i - n4h); }
    else if (i < n4h + n4q + n4p) { in = wproj_in + (i - n4h - n4q); out = wproj_out + (i - n4h - n4q); }
    else return;
    float4 v = *in;
    v.x = to_tf32(v.x); v.y = to_tf32(v.y);
    v.z = to_tf32(v.z); v.w = to_tf32(v.w);
    *out = v;
}

// ---------------- RoPE + tf32 round pass (in place on g_qkv) ------
__global__ __launch_bounds__(128)
void rope_round_kernel(float* __restrict__ qkv,
                       const float* __restrict__ freqs)   // [T,40]
{
    const int row = blockIdx.x;
    const int t   = row >> 8;            // row = t*256 + s
    float* r = qkv + (size_t)row * QKVD;

    __shared__ float cs[40], sn[40];
    if (threadIdx.x < 40) {
        const float f = freqs[t * 40 + threadIdx.x];
        cs[threadIdx.x] = cosf(f);
        sn[threadIdx.x] = sinf(f);
    }
    __syncthreads();

    for (int i = threadIdx.x; i < 320; i += 128) {
        const int sec = i / 160;         // 0=Q, 1=K
        const int hh  = (i % 160) / 40;
        const int j   = i % 40;
        float* p = r + sec * NECK + hh * HDIM;
        const float x1 = p[j], x2 = p[j + 40];
        p[j]      = to_tf32(x1 * cs[j] - x2 * sn[j]);
        p[j + 40] = to_tf32(x2 * cs[j] + x1 * sn[j]);
    }
    for (int i = threadIdx.x; i < NECK; i += 128)
        r[2 * NECK + i] = to_tf32(r[2 * NECK + i]);
}

// ---------------- Tensor-core flash attention (unchanged) ---------
#define ATT_SMEM ((20480 + 20480 + 8192) * 4)

#define PADDR(r, ck) ((((ck) >> 4) << 8) + ((r) << 4) + \
                      ((((ck) & 3) ^ ((r) & 3)) << 2) + (((ck) >> 2) & 3))

__global__ __launch_bounds__(256)
void attn_tc_kernel(const float* __restrict__ qkv,
                    float* __restrict__ attout)
{
    extern __shared__ float sh[];
    float* Ks = sh;
    float* Vs = sh + 20480;

    const int s    = blockIdx.x;
    const int h    = blockIdx.y;
    const int tid  = threadIdx.x;
    const int lane = tid & 31;
    const int w    = tid >> 5;
    const int g    = lane >> 2;
    const int t4   = lane & 3;
    const int hb   = h * HDIM;

    for (int i = tid; i < TC * HDIM; i += 256) {
        const int t = i / HDIM, d = i % HDIM;
        const float v = qkv[(size_t)(t * S1C + s) * QKVD + NECK + hb + d];
        Ks[t * 80 + ((d >> 4) << 4) + (((d & 3) ^ (t & 3)) << 2) + ((d >> 2) & 3)] = v;
    }
    for (int i = tid; i < TC * HDIM; i += 256) {
        const int t = i / HDIM, d = i % HDIM;
        const float v = qkv[(size_t)(t * S1C + s) * QKVD + 2 * NECK + hb + d];
        Vs[(t >> 4) * 1280 + (d << 4) + (((t & 3) ^ (d & 3)) << 2) + ((t >> 2) & 3)] = v;
    }
    __syncthreads();

    float* Pw = sh + 40960 + w * 1024;
    const float scale = 0.111803398874989484f;   // 1/sqrt(80)
    const int swg = ((t4 ^ (g & 3)) << 2);

    #pragma unroll
    for (int rg = 0; rg < 2; rg++) {
        const int R0 = w * 32 + rg * 16;

        float4 qa[5], qb[5];
        {
            const float* p0 = qkv + (size_t)((R0 + g) * S1C + s) * QKVD + hb + t4;
            const float* p1 = qkv + (size_t)((R0 + g + 8) * S1C + s) * QKVD + hb + t4;
            #pragma unroll
            for (int b = 0; b < 5; b++) {
                qa[b] = make_float4(p0[b*16], p0[b*16+4], p0[b*16+8], p0[b*16+12]);
                qb[b] = make_float4(p1[b*16], p1[b*16+4], p1[b*16+8], p1[b*16+12]);
            }
        }

        float m0 = -1e30f, m1 = -1e30f, l0 = 0.f, l1 = 0.f;
        float4 o[10];
        #pragma unroll
        for (int dt = 0; dt < 10; dt++) o[dt] = make_float4(0.f, 0.f, 0.f, 0.f);

        for (int c = 0; c < 4; c++) {
            float4 sacc[8];
            #pragma unroll
            for (int nt = 0; nt < 8; nt++) sacc[nt] = make_float4(0.f, 0.f, 0.f, 0.f);
            #pragma unroll
            for (int nt = 0; nt < 8; nt++) {
                const int krow = c * 64 + nt * 8 + g;
                const float* pb = Ks + krow * 80 + swg;
                #pragma unroll
                for (int b = 0; b < 5; b++) {
                    const float4 fb = *(const float4*)(pb + b * 16);
                    mma_tf32(sacc[nt], qa[b].x, qb[b].x, qa[b].y, qb[b].y, fb.x, fb.y);
                    mma_tf32(sacc[nt], qa[b].z, qb[b].z, qa[b].w, qb[b].w, fb.z, fb.w);
                }
            }

            float mx0 = -1e30f, mx1 = -1e30f;
            #pragma unroll
            for (int nt = 0; nt < 8; nt++) {
                sacc[nt].x *= scale; sacc[nt].y *= scale;
                sacc[nt].z *= scale; sacc[nt].w *= scale;
                mx0 = fmaxf(mx0, fmaxf(sacc[nt].x, sacc[nt].y));
                mx1 = fmaxf(mx1, fmaxf(sacc[nt].z, sacc[nt].w));
            }
            mx0 = fmaxf(mx0, __shfl_xor_sync(0xffffffffu, mx0, 1));
            mx0 = fmaxf(mx0, __shfl_xor_sync(0xffffffffu, mx0, 2));
            mx1 = fmaxf(mx1, __shfl_xor_sync(0xffffffffu, mx1, 1));
            mx1 = fmaxf(mx1, __shfl_xor_sync(0xffffffffu, mx1, 2));

            const float mn0 = fmaxf(m0, mx0), mn1 = fmaxf(m1, mx1);
            const float cor0 = __expf(m0 - mn0), cor1 = __expf(m1 - mn1);

            float s0 = 0.f, s1 = 0.f;
            #pragma unroll
            for (int nt = 0; nt < 8; nt++) {
                sacc[nt].x = __expf(sacc[nt].x - mn0); s0 += sacc[nt].x;
                sacc[nt].y = __expf(sacc[nt].y - mn0); s0 += sacc[nt].y;
                sacc[nt].z = __expf(sacc[nt].z - mn1); s1 += sacc[nt].z;
                sacc[nt].w = __expf(sacc[nt].w - mn1); s1 += sacc[nt].w;
            }
            s0 += __shfl_xor_sync(0xffffffffu, s0, 1);
            s0 += __shfl_xor_sync(0xffffffffu, s0, 2);
            s1 += __shfl_xor_sync(0xffffffffu, s1, 1);
            s1 += __shfl_xor_sync(0xffffffffu, s1, 2);

            l0 = l0 * cor0 + s0;  l1 = l1 * cor1 + s1;
            m0 = mn0;             m1 = mn1;

            #pragma unroll
            for (int dt = 0; dt < 10; dt++) {
                o[dt].x *= cor0; o[dt].y *= cor0;
                o[dt].z *= cor1; o[dt].w *= cor1;
            }

            __syncwarp();
            #pragma unroll
            for (int nt = 0; nt < 8; nt++) {
                const int ck0 = nt * 8 + 2 * t4;
                Pw[PADDR(g,     ck0    )] = to_tf32(sacc[nt].x);
                Pw[PADDR(g,     ck0 + 1)] = to_tf32(sacc[nt].y);
                Pw[PADDR(g + 8, ck0    )] = to_tf32(sacc[nt].z);
                Pw[PADDR(g + 8, ck0 + 1)] = to_tf32(sacc[nt].w);
            }
            __syncwarp();

            float4 pa[4], pc[4];
            #pragma unroll
            for (int kb = 0; kb < 4; kb++) {
                const float* pp = Pw + kb * 256 + g * 16 + swg;
                pa[kb] = *(const float4*)(pp);
                pc[kb] = *(const float4*)(pp + 128);
            }
            #pragma unroll
            for (int dt = 0; dt < 10; dt++) {
                const int drow = dt * 8 + g;
                const float* pv = Vs + (c * 4) * 1280 + drow * 16 + swg;
                #pragma unroll
                for (int kb = 0; kb < 4; kb++) {
                    const float4 fv = *(const float4*)(pv + kb * 1280);
                    mma_tf32(o[dt], pa[kb].x, pc[kb].x, pa[kb].y, pc[kb].y, fv.x, fv.y);
                    mma_tf32(o[dt], pa[kb].z, pc[kb].z, pa[kb].w, pc[kb].w, fv.z, fv.w);
                }
            }
        }

        const float il0 = 1.f / l0, il1 = 1.f / l1;
        const int col = hb + 2 * t4;
        #pragma unroll
        for (int dt = 0; dt < 10; dt++) {
            float2 v0 = make_float2(to_tf32(o[dt].x * il0), to_tf32(o[dt].y * il0));
            float2 v1 = make_float2(to_tf32(o[dt].z * il1), to_tf32(o[dt].w * il1));
            *(float2*)(attout + (size_t)(s * TC + R0 + g)     * NECK + col + dt * 8) = v0;
            *(float2*)(attout + (size_t)(s * TC + R0 + g + 8) * NECK + col + dt * 8) = v1;
        }
    }
}

// ---------------- Launch -------------------------------------------
extern "C" void kernel_launch(void* const* d_in, const int* in_sizes, int n_in,
                              void* d_out, int out_size)
{
    const float* hidden = (const float*)d_in[0];
    const float* freqs  = (const float*)d_in[2];
    const float* w_qkv  = (const float*)d_in[3];
    const float* b_qkv  = (const float*)d_in[4];
    const float* w_proj = (const float*)d_in[5];
    const float* b_proj = (const float*)d_in[6];
    float* out = (float*)d_out;

    float *qkv_p, *att_p, *hid_p, *wqkv_p, *wproj_p;
    cudaGetSymbolAddress((void**)&qkv_p,   g_qkv);
    cudaGetSymbolAddress((void**)&att_p,   g_att);
    cudaGetSymbolAddress((void**)&hid_p,   g_hid);
    cudaGetSymbolAddress((void**)&wqkv_p,  g_wqkv);
    cudaGetSymbolAddress((void**)&wproj_p, g_wproj);

    // 0) tf32-round inputs once (single fused launch)
    {
        const int n4 = (SEQ * EMBED + QKVD * EMBED + EMBED * NECK) / 4;
        cvt_all_kernel<<<(n4 + 255) / 256, 256>>>(
            (const float4*)hidden, (const float4*)w_qkv, (const float4*)w_proj,
            (float4*)hid_p, (float4*)wqkv_p, (float4*)wproj_p);
    }

    // 1) QKV GEMM: [65536,960] = hid @ w_qkv^T + b_qkv   (K=1280)
    {
        dim3 grid((QKVD + 127) / 128, SEQ / 128);   // 8 x 512
        gemm_tf32_tn_bias<<<grid, 256>>>(hid_p, wqkv_p, b_qkv, qkv_p,
                                         SEQ, QKVD, EMBED);
    }

    // 1.5) RoPE + tf32 round (in place on g_qkv)
    rope_round_kernel<<<SEQ, 128>>>(qkv_p, freqs);

    // 2) Tensor-core attention -> g_att (tf32)
    {
        cudaFuncSetAttribute(attn_tc_kernel,
                             cudaFuncAttributeMaxDynamicSharedMemorySize, ATT_SMEM);
        dim3 grid(S1C, NHEAD);
        attn_tc_kernel<<<grid, 256, ATT_SMEM>>>(qkv_p, att_p);
    }

    // 3) Proj GEMM: out[65536,1280] = att @ w_proj^T + b_proj  (K=320)
    {
        dim3 grid(EMBED / 128, SEQ / 128);          // 10 x 512
        gemm_tf32_tn_bias<<<grid, 256>>>(att_p, wproj_p, b_proj, out,
                                         SEQ, EMBED, NECK);
    }
}

// round 7
// speedup vs baseline: 1.4387x; 1.4387x over previous
#include <cuda_runtime.h>
#include <cuda_bf16.h>
#include <math.h>
#include <stdint.h>

// ---------------- Problem constants (fixed shapes) ----------------
#define SEQ       65536
#define EMBED     1280
#define NECK      320
#define QKVD      960      // 3 * NECK
#define NHEAD     4
#define HDIM      80
#define S1C       256
#define TC        256

// ---------------- Scratch (alloc-free: __device__ globals) --------
__device__ float g_qkv[(size_t)SEQ * QKVD];     // [t*S1+s, 960]
__device__ float g_att[(size_t)SEQ * NECK];     // [s*T+t, 320] (tf32)
__device__ float g_hid[(size_t)SEQ * EMBED];    // tf32 hidden
__device__ float g_wqkv[(size_t)QKVD * EMBED];  // tf32 w_qkv
__device__ float g_wproj[(size_t)EMBED * NECK]; // tf32 w_proj

// ================= helpers ========================================
__device__ __forceinline__ float to_tf32(float x) {
    uint32_t u;
    asm("cvt.rna.tf32.f32 %0, %1;" : "=r"(u) : "f"(x));
    return __uint_as_float(u);
}

__device__ __forceinline__ uint32_t smem_u32(const void* p) {
    uint32_t a;
    asm("{ .reg .u64 t; cvta.to.shared.u64 t, %1; cvt.u32.u64 %0, t; }"
        : "=r"(a) : "l"(p));
    return a;
}

__device__ __forceinline__ void mma_tf32(float4& d,
    float a0, float a1, float a2, float a3, float b0, float b1)
{
    asm volatile(
        "mma.sync.aligned.m16n8k8.row.col.f32.tf32.tf32.f32 "
        "{%0,%1,%2,%3}, {%4,%5,%6,%7}, {%8,%9}, {%0,%1,%2,%3};\n"
        : "+f"(d.x), "+f"(d.y), "+f"(d.z), "+f"(d.w)
        : "r"(__float_as_uint(a0)), "r"(__float_as_uint(a1)),
          "r"(__float_as_uint(a2)), "r"(__float_as_uint(a3)),
          "r"(__float_as_uint(b0)), "r"(__float_as_uint(b1)));
}

__device__ __forceinline__ void mma_tf32u(float4& d,
    uint32_t a0, uint32_t a1, uint32_t a2, uint32_t a3,
    uint32_t b0, uint32_t b1)
{
    asm volatile(
        "mma.sync.aligned.m16n8k8.row.col.f32.tf32.tf32.f32 "
        "{%0,%1,%2,%3}, {%4,%5,%6,%7}, {%8,%9}, {%0,%1,%2,%3};\n"
        : "+f"(d.x), "+f"(d.y), "+f"(d.z), "+f"(d.w)
        : "r"(a0), "r"(a1), "r"(a2), "r"(a3), "r"(b0), "r"(b1));
}

__device__ __forceinline__ void ldsm_x4(uint32_t& r0, uint32_t& r1,
                                        uint32_t& r2, uint32_t& r3,
                                        uint32_t addr)
{
    asm volatile("ldmatrix.sync.aligned.m8n8.x4.shared.b16 {%0,%1,%2,%3}, [%4];"
                 : "=r"(r0), "=r"(r1), "=r"(r2), "=r"(r3) : "r"(addr));
}

__device__ __forceinline__ void cp_async16z(uint32_t dst, const void* src, bool valid) {
    int sz = valid ? 16 : 0;
    asm volatile("cp.async.cg.shared.global [%0], [%1], 16, %2;"
                 :: "r"(dst), "l"(src), "r"(sz));
}
#define CP_COMMIT()  asm volatile("cp.async.commit_group;" ::: "memory")
#define CP_WAIT1()   asm volatile("cp.async.wait_group 1;" ::: "memory")
#define CP_WAIT0()   asm volatile("cp.async.wait_group 0;" ::: "memory")

// ================= TF32 tensor-core GEMM (cp.async + ldmatrix) ====
// C[M,N] = A[M,K] @ B[N,K]^T + bias[N]; A,B already tf32-rounded.
// Block 128x256, BK=16, 256 threads (8 warps), warp tile 64x64.
// 3-stage cp.async ring. Smem rows = 64B (4 x 16B chunks), swizzle:
//   phys_chunk = chunk ^ (r&3) ^ ((r>>2)&1)   (bank-conflict-free for
//   both 8-rows-x-4-chunks cp.async stores and ldmatrix 8x16B reads)
#define STG_A     8192                   // 128 rows * 64B
#define STG_B     16384                  // 256 rows * 64B
#define STG_BYTES (STG_A + STG_B)
#define GSTAGES   3
#define GEMM_SMEM (GSTAGES * STG_BYTES)  // 73728

__global__ __launch_bounds__(256)
void gemm_tc(const float* __restrict__ A, const float* __restrict__ B,
             const float* __restrict__ bias, float* __restrict__ C,
             int M, int N, int K)
{
    extern __shared__ char smem[];
    const uint32_t sb = smem_u32(smem);

    const int tid  = threadIdx.x;
    const int lane = tid & 31;
    const int warp = tid >> 5;
    const int wm   = warp >> 2;          // 0..1
    const int wn   = warp & 3;           // 0..3
    const int g    = lane >> 2;
    const int t4   = lane & 3;

    const int bm = blockIdx.y * 128;
    const int bn = blockIdx.x * 256;

    // ldmatrix per-lane base addresses
    const int rA  = wm * 64 + (lane & 15);
    const int hiA = lane >> 4;                       // 0|1 -> k-chunk parity
    const int kAx = (rA & 3) ^ ((rA >> 2) & 1);
    const uint32_t baseA = (uint32_t)(rA * 64 + 16 * (hiA ^ kAx));

    const int rB  = wn * 64 + (lane & 7);
    const int cB  = lane >> 3;                       // 0..3 -> k-chunk
    const int kBx = (rB & 3) ^ ((rB >> 2) & 1);
    const uint32_t baseB = (uint32_t)(STG_A + rB * 64 + 16 * (cB ^ kBx));

    float4 acc[4][8];
    #pragma unroll
    for (int i = 0; i < 4; i++)
        #pragma unroll
        for (int j = 0; j < 8; j++)
            acc[i][j] = make_float4(0.f, 0.f, 0.f, 0.f);

    const int KT = K >> 4;

    // stage loader: A 512 chunks (2/thread), B 1024 chunks (4/thread)
    #define LOADST(s, bufi) do {                                              \
        const uint32_t st_ = sb + (bufi) * STG_BYTES;                         \
        _Pragma("unroll")                                                     \
        for (int i = 0; i < 2; i++) {                                         \
            const int idx = i * 256 + tid;                                    \
            const int r = idx >> 2, kc = idx & 3;                             \
            const int sc = kc ^ (r & 3) ^ ((r >> 2) & 1);                     \
            cp_async16z(st_ + r * 64 + 16 * sc,                               \
                        A + (size_t)(bm + r) * K + (s) * 16 + kc * 4, true);  \
        }                                                                     \
        _Pragma("unroll")                                                     \
        for (int i = 0; i < 4; i++) {                                         \
            const int idx = i * 256 + tid;                                    \
            const int r = idx >> 2, kc = idx & 3;                             \
            const int sc = kc ^ (r & 3) ^ ((r >> 2) & 1);                     \
            const bool v = (bn + r) < N;                                      \
            cp_async16z(st_ + STG_A + r * 64 + 16 * sc,                       \
                        B + (size_t)(v ? (bn + r) : 0) * K + (s) * 16 + kc * 4, v); \
        }                                                                     \
        CP_COMMIT();                                                          \
    } while (0)

    LOADST(0, 0);
    LOADST(1, 1);

    int buf = 0;
    for (int kt = 0; kt < KT; kt++) {
        if (kt < KT - 1) { CP_WAIT1(); } else { CP_WAIT0(); }
        __syncthreads();
        const uint32_t st = sb + buf * STG_BYTES;

        // A fragments: 4 m-tiles x 2 k-steps, one ldmatrix.x4 each
        uint32_t af[4][2][4];
        #pragma unroll
        for (int mt = 0; mt < 4; mt++) {
            const uint32_t a0 = st + baseA + mt * 1024;
            ldsm_x4(af[mt][0][0], af[mt][0][1], af[mt][0][2], af[mt][0][3], a0);
            ldsm_x4(af[mt][1][0], af[mt][1][1], af[mt][1][2], af[mt][1][3], a0 ^ 32);
        }
        // B fragments: 8 n-tiles, one ldmatrix.x4 covers both k-steps
        uint32_t bf[8][4];
        #pragma unroll
        for (int nt = 0; nt < 8; nt++)
            ldsm_x4(bf[nt][0], bf[nt][1], bf[nt][2], bf[nt][3],
                    st + baseB + nt * 512);

        #pragma unroll
        for (int mt = 0; mt < 4; mt++)
            #pragma unroll
            for (int nt = 0; nt < 8; nt++) {
                mma_tf32u(acc[mt][nt],
                          af[mt][0][0], af[mt][0][1], af[mt][0][2], af[mt][0][3],
                          bf[nt][0], bf[nt][1]);
                mma_tf32u(acc[mt][nt],
                          af[mt][1][0], af[mt][1][1], af[mt][1][2], af[mt][1][3],
                          bf[nt][2], bf[nt][3]);
            }

        if (kt + 2 < KT) {
            int nb = buf + 2; if (nb >= GSTAGES) nb -= GSTAGES;
            LOADST(kt + 2, nb);
        }
        buf++; if (buf == GSTAGES) buf = 0;
    }
    #undef LOADST

    // -------- epilogue: bias + store --------
    #pragma unroll
    for (int mt = 0; mt < 4; mt++) {
        const int row = bm + wm * 64 + mt * 16 + g;
        #pragma unroll
        for (int nt = 0; nt < 8; nt++) {
            const int col = bn + wn * 64 + nt * 8 + 2 * t4;
            if (col < N) {
                const float bx = __ldg(bias + col), by = __ldg(bias + col + 1);
                float2 v0 = make_float2(acc[mt][nt].x + bx, acc[mt][nt].y + by);
                float2 v1 = make_float2(acc[mt][nt].z + bx, acc[mt][nt].w + by);
                *(float2*)(C + (size_t)row * N + col)       = v0;
                *(float2*)(C + (size_t)(row + 8) * N + col) = v1;
            }
        }
    }
}

// ---------------- tf32 pre-rounding kernel (single launch) --------
__global__ void cvt_all_kernel(const float4* __restrict__ hid_in,
                               const float4* __restrict__ wqkv_in,
                               const float4* __restrict__ wproj_in,
                               float4* __restrict__ hid_out,
                               float4* __restrict__ wqkv_out,
                               float4* __restrict__ wproj_out)
{
    const int n4h = (SEQ * EMBED) / 4;
    const int n4q = (QKVD * EMBED) / 4;
    const int n4p = (EMBED * NECK) / 4;
    int i = blockIdx.x * blockDim.x + threadIdx.x;
    const float4* in;
    float4* out;
    if (i < n4h)            { in = hid_in + i;                 out = hid_out + i; }
    else if (i < n4h + n4q) { in = wqkv_in + (i - n4h);        out = wqkv_out + (i - n4h); }
    else if (i < n4h + n4q + n4p) { in = wproj_in + (i - n4h - n4q); out = wproj_out + (i - n4h - n4q); }
    else return;
    float4 v = *in;
    v.x = to_tf32(v.x); v.y = to_tf32(v.y);
    v.z = to_tf32(v.z); v.w = to_tf32(v.w);
    *out = v;
}

// ---------------- RoPE + tf32 round pass (in place on g_qkv) ------
__global__ __launch_bounds__(128)
void rope_round_kernel(float* __restrict__ qkv,
                       const float* __restrict__ freqs)   // [T,40]
{
    const int row = blockIdx.x;
    const int t   = row >> 8;            // row = t*256 + s
    float* r = qkv + (size_t)row * QKVD;

    __shared__ float cs[40], sn[40];
    if (threadIdx.x < 40) {
        const float f = freqs[t * 40 + threadIdx.x];
        cs[threadIdx.x] = cosf(f);
        sn[threadIdx.x] = sinf(f);
    }
    __syncthreads();

    for (int i = threadIdx.x; i < 320; i += 128) {
        const int sec = i / 160;         // 0=Q, 1=K
        const int hh  = (i % 160) / 40;
        const int j   = i % 40;
        float* p = r + sec * NECK + hh * HDIM;
        const float x1 = p[j], x2 = p[j + 40];
        p[j]      = to_tf32(x1 * cs[j] - x2 * sn[j]);
        p[j + 40] = to_tf32(x2 * cs[j] + x1 * sn[j]);
    }
    for (int i = threadIdx.x; i < NECK; i += 128)
        r[2 * NECK + i] = to_tf32(r[2 * NECK + i]);
}

// ---------------- Tensor-core flash attention (R5, unchanged) -----
#define ATT_SMEM ((20480 + 20480 + 8192) * 4)

#define PADDR(r, ck) ((((ck) >> 4) << 8) + ((r) << 4) + \
                      ((((ck) & 3) ^ ((r) & 3)) << 2) + (((ck) >> 2) & 3))

__global__ __launch_bounds__(256)
void attn_tc_kernel(const float* __restrict__ qkv,
                    float* __restrict__ attout)
{
    extern __shared__ float sh[];
    float* Ks = sh;
    float* Vs = sh + 20480;

    const int s    = blockIdx.x;
    const int h    = blockIdx.y;
    const int tid  = threadIdx.x;
    const int lane = tid & 31;
    const int w    = tid >> 5;
    const int g    = lane >> 2;
    const int t4   = lane & 3;
    const int hb   = h * HDIM;

    for (int i = tid; i < TC * HDIM; i += 256) {
        const int t = i / HDIM, d = i % HDIM;
        const float v = qkv[(size_t)(t * S1C + s) * QKVD + NECK + hb + d];
        Ks[t * 80 + ((d >> 4) << 4) + (((d & 3) ^ (t & 3)) << 2) + ((d >> 2) & 3)] = v;
    }
    for (int i = tid; i < TC * HDIM; i += 256) {
        const int t = i / HDIM, d = i % HDIM;
        const float v = qkv[(size_t)(t * S1C + s) * QKVD + 2 * NECK + hb + d];
        Vs[(t >> 4) * 1280 + (d << 4) + (((t & 3) ^ (d & 3)) << 2) + ((t >> 2) & 3)] = v;
    }
    __syncthreads();

    float* Pw = sh + 40960 + w * 1024;
    const float scale = 0.111803398874989484f;   // 1/sqrt(80)
    const int swg = ((t4 ^ (g & 3)) << 2);

    #pragma unroll
    for (int rg = 0; rg < 2; rg++) {
        const int R0 = w * 32 + rg * 16;

        float4 qa[5], qb[5];
        {
            const float* p0 = qkv + (size_t)((R0 + g) * S1C + s) * QKVD + hb + t4;
            const float* p1 = qkv + (size_t)((R0 + g + 8) * S1C + s) * QKVD + hb + t4;
            #pragma unroll
            for (int b = 0; b < 5; b++) {
                qa[b] = make_float4(p0[b*16], p0[b*16+4], p0[b*16+8], p0[b*16+12]);
                qb[b] = make_float4(p1[b*16], p1[b*16+4], p1[b*16+8], p1[b*16+12]);
            }
        }

        float m0 = -1e30f, m1 = -1e30f, l0 = 0.f, l1 = 0.f;
        float4 o[10];
        #pragma unroll
        for (int dt = 0; dt < 10; dt++) o[dt] = make_float4(0.f, 0.f, 0.f, 0.f);

        for (int c = 0; c < 4; c++) {
            float4 sacc[8];
            #pragma unroll
            for (int nt = 0; nt < 8; nt++) sacc[nt] = make_float4(0.f, 0.f, 0.f, 0.f);
            #pragma unroll
            for (int nt = 0; nt < 8; nt++) {
                const int krow = c * 64 + nt * 8 + g;
                const float* pb = Ks + krow * 80 + swg;
                #pragma unroll
                for (int b = 0; b < 5; b++) {
                    const float4 fb = *(const float4*)(pb + b * 16);
                    mma_tf32(sacc[nt], qa[b].x, qb[b].x, qa[b].y, qb[b].y, fb.x, fb.y);
                    mma_tf32(sacc[nt], qa[b].z, qb[b].z, qa[b].w, qb[b].w, fb.z, fb.w);
                }
            }

            float mx0 = -1e30f, mx1 = -1e30f;
            #pragma unroll
            for (int nt = 0; nt < 8; nt++) {
                sacc[nt].x *= scale; sacc[nt].y *= scale;
                sacc[nt].z *= scale; sacc[nt].w *= scale;
                mx0 = fmaxf(mx0, fmaxf(sacc[nt].x, sacc[nt].y));
                mx1 = fmaxf(mx1, fmaxf(sacc[nt].z, sacc[nt].w));
            }
            mx0 = fmaxf(mx0, __shfl_xor_sync(0xffffffffu, mx0, 1));
            mx0 = fmaxf(mx0, __shfl_xor_sync(0xffffffffu, mx0, 2));
            mx1 = fmaxf(mx1, __shfl_xor_sync(0xffffffffu, mx1, 1));
            mx1 = fmaxf(mx1, __shfl_xor_sync(0xffffffffu, mx1, 2));

            const float mn0 = fmaxf(m0, mx0), mn1 = fmaxf(m1, mx1);
            const float cor0 = __expf(m0 - mn0), cor1 = __expf(m1 - mn1);

            float s0 = 0.f, s1 = 0.f;
            #pragma unroll
            for (int nt = 0; nt < 8; nt++) {
                sacc[nt].x = __expf(sacc[nt].x - mn0); s0 += sacc[nt].x;
                sacc[nt].y = __expf(sacc[nt].y - mn0); s0 += sacc[nt].y;
                sacc[nt].z = __expf(sacc[nt].z - mn1); s1 += sacc[nt].z;
                sacc[nt].w = __expf(sacc[nt].w - mn1); s1 += sacc[nt].w;
            }
            s0 += __shfl_xor_sync(0xffffffffu, s0, 1);
            s0 += __shfl_xor_sync(0xffffffffu, s0, 2);
            s1 += __shfl_xor_sync(0xffffffffu, s1, 1);
            s1 += __shfl_xor_sync(0xffffffffu, s1, 2);

            l0 = l0 * cor0 + s0;  l1 = l1 * cor1 + s1;
            m0 = mn0;             m1 = mn1;

            #pragma unroll
            for (int dt = 0; dt < 10; dt++) {
                o[dt].x *= cor0; o[dt].y *= cor0;
                o[dt].z *= cor1; o[dt].w *= cor1;
            }

            __syncwarp();
            #pragma unroll
            for (int nt = 0; nt < 8; nt++) {
                const int ck0 = nt * 8 + 2 * t4;
                Pw[PADDR(g,     ck0    )] = to_tf32(sacc[nt].x);
                Pw[PADDR(g,     ck0 + 1)] = to_tf32(sacc[nt].y);
                Pw[PADDR(g + 8, ck0    )] = to_tf32(sacc[nt].z);
                Pw[PADDR(g + 8, ck0 + 1)] = to_tf32(sacc[nt].w);
            }
            __syncwarp();

            float4 pa[4], pc[4];
            #pragma unroll
            for (int kb = 0; kb < 4; kb++) {
                const float* pp = Pw + kb * 256 + g * 16 + swg;
                pa[kb] = *(const float4*)(pp);
                pc[kb] = *(const float4*)(pp + 128);
            }
            #pragma unroll
            for (int dt = 0; dt < 10; dt++) {
                const int drow = dt * 8 + g;
                const float* pv = Vs + (c * 4) * 1280 + drow * 16 + swg;
                #pragma unroll
                for (int kb = 0; kb < 4; kb++) {
                    const float4 fv = *(const float4*)(pv + kb * 1280);
                    mma_tf32(o[dt], pa[kb].x, pc[kb].x, pa[kb].y, pc[kb].y, fv.x, fv.y);
                    mma_tf32(o[dt], pa[kb].z, pc[kb].z, pa[kb].w, pc[kb].w, fv.z, fv.w);
                }
            }
        }

        const float il0 = 1.f / l0, il1 = 1.f / l1;
        const int col = hb + 2 * t4;
        #pragma unroll
        for (int dt = 0; dt < 10; dt++) {
            float2 v0 = make_float2(to_tf32(o[dt].x * il0), to_tf32(o[dt].y * il0));
            float2 v1 = make_float2(to_tf32(o[dt].z * il1), to_tf32(o[dt].w * il1));
            *(float2*)(attout + (size_t)(s * TC + R0 + g)     * NECK + col + dt * 8) = v0;
            *(float2*)(attout + (size_t)(s * TC + R0 + g + 8) * NECK + col + dt * 8) = v1;
        }
    }
}

// ---------------- Launch -------------------------------------------
extern "C" void kernel_launch(void* const* d_in, const int* in_sizes, int n_in,
                              void* d_out, int out_size)
{
    const float* hidden = (const float*)d_in[0];
    const float* freqs  = (const float*)d_in[2];
    const float* w_qkv  = (const float*)d_in[3];
    const float* b_qkv  = (const float*)d_in[4];
    const float* w_proj = (const float*)d_in[5];
    const float* b_proj = (const float*)d_in[6];
    float* out = (float*)d_out;

    float *qkv_p, *att_p, *hid_p, *wqkv_p, *wproj_p;
    cudaGetSymbolAddress((void**)&qkv_p,   g_qkv);
    cudaGetSymbolAddress((void**)&att_p,   g_att);
    cudaGetSymbolAddress((void**)&hid_p,   g_hid);
    cudaGetSymbolAddress((void**)&wqkv_p,  g_wqkv);
    cudaGetSymbolAddress((void**)&wproj_p, g_wproj);

    // 0) tf32-round inputs once (single fused launch)
    {
        const int n4 = (SEQ * EMBED + QKVD * EMBED + EMBED * NECK) / 4;
        cvt_all_kernel<<<(n4 + 255) / 256, 256>>>(
            (const float4*)hidden, (const float4*)w_qkv, (const float4*)w_proj,
            (float4*)hid_p, (float4*)wqkv_p, (float4*)wproj_p);
    }

    // 1) QKV GEMM: [65536,960] = hid @ w_qkv^T + b_qkv   (K=1280)
    {
        cudaFuncSetAttribute(gemm_tc,
                             cudaFuncAttributeMaxDynamicSharedMemorySize, GEMM_SMEM);
        dim3 grid((QKVD + 255) / 256, SEQ / 128);   // 4 x 512
        gemm_tc<<<grid, 256, GEMM_SMEM>>>(hid_p, wqkv_p, b_qkv, qkv_p,
                                          SEQ, QKVD, EMBED);
    }

    // 1.5) RoPE + tf32 round (in place on g_qkv)
    rope_round_kernel<<<SEQ, 128>>>(qkv_p, freqs);

    // 2) Tensor-core attention -> g_att (tf32)
    {
        cudaFuncSetAttribute(attn_tc_kernel,
                             cudaFuncAttributeMaxDynamicSharedMemorySize, ATT_SMEM);
        dim3 grid(S1C, NHEAD);
        attn_tc_kernel<<<grid, 256, ATT_SMEM>>>(qkv_p, att_p);
    }

    // 3) Proj GEMM: out[65536,1280] = att @ w_proj^T + b_proj  (K=320)
    {
        dim3 grid(EMBED / 256, SEQ / 128);          // 5 x 512
        gemm_tc<<<grid, 256, GEMM_SMEM>>>(att_p, wproj_p, b_proj, out,
                                          SEQ, EMBED, NECK);
    }
}

// round 8
// speedup vs baseline: 1.6975x; 1.1799x over previous
#include <cuda_runtime.h>
#include <cuda_bf16.h>
#include <math.h>
#include <stdint.h>

// ---------------- Problem constants (fixed shapes) ----------------
#define SEQ       65536
#define EMBED     1280
#define NECK      320
#define QKVD      960      // 3 * NECK
#define NHEAD     4
#define HDIM      80
#define S1C       256
#define TC        256

// ---------------- Scratch (alloc-free: __device__ globals) --------
__device__ float g_qkv[(size_t)SEQ * QKVD];     // [t*S1+s, 960]
__device__ float g_att[(size_t)SEQ * NECK];     // [s*T+t, 320] (tf32)
__device__ float g_hid[(size_t)SEQ * EMBED];    // tf32 hidden
__device__ float g_wqkv[(size_t)QKVD * EMBED];  // tf32 w_qkv
__device__ float g_wproj[(size_t)EMBED * NECK]; // tf32 w_proj

// ================= helpers ========================================
__device__ __forceinline__ float to_tf32(float x) {
    uint32_t u;
    asm("cvt.rna.tf32.f32 %0, %1;" : "=r"(u) : "f"(x));
    return __uint_as_float(u);
}

__device__ __forceinline__ uint32_t smem_u32(const void* p) {
    uint32_t a;
    asm("{ .reg .u64 t; cvta.to.shared.u64 t, %1; cvt.u32.u64 %0, t; }"
        : "=r"(a) : "l"(p));
    return a;
}

__device__ __forceinline__ void mma_tf32(float4& d,
    float a0, float a1, float a2, float a3, float b0, float b1)
{
    asm volatile(
        "mma.sync.aligned.m16n8k8.row.col.f32.tf32.tf32.f32 "
        "{%0,%1,%2,%3}, {%4,%5,%6,%7}, {%8,%9}, {%0,%1,%2,%3};\n"
        : "+f"(d.x), "+f"(d.y), "+f"(d.z), "+f"(d.w)
        : "r"(__float_as_uint(a0)), "r"(__float_as_uint(a1)),
          "r"(__float_as_uint(a2)), "r"(__float_as_uint(a3)),
          "r"(__float_as_uint(b0)), "r"(__float_as_uint(b1)));
}

__device__ __forceinline__ void mma_tf32u(float4& d,
    uint32_t a0, uint32_t a1, uint32_t a2, uint32_t a3,
    uint32_t b0, uint32_t b1)
{
    asm volatile(
        "mma.sync.aligned.m16n8k8.row.col.f32.tf32.tf32.f32 "
        "{%0,%1,%2,%3}, {%4,%5,%6,%7}, {%8,%9}, {%0,%1,%2,%3};\n"
        : "+f"(d.x), "+f"(d.y), "+f"(d.z), "+f"(d.w)
        : "r"(a0), "r"(a1), "r"(a2), "r"(a3), "r"(b0), "r"(b1));
}

__device__ __forceinline__ void ldsm_x4(uint32_t& r0, uint32_t& r1,
                                        uint32_t& r2, uint32_t& r3,
                                        uint32_t addr)
{
    asm volatile("ldmatrix.sync.aligned.m8n8.x4.shared.b16 {%0,%1,%2,%3}, [%4];"
                 : "=r"(r0), "=r"(r1), "=r"(r2), "=r"(r3) : "r"(addr));
}

__device__ __forceinline__ void cp_async16z(uint32_t dst, const void* src, bool valid) {
    int sz = valid ? 16 : 0;
    asm volatile("cp.async.cg.shared.global [%0], [%1], 16, %2;"
                 :: "r"(dst), "l"(src), "r"(sz));
}
#define CP_COMMIT()  asm volatile("cp.async.commit_group;" ::: "memory")
#define CP_WAIT1()   asm volatile("cp.async.wait_group 1;" ::: "memory")
#define CP_WAIT0()   asm volatile("cp.async.wait_group 0;" ::: "memory")

// ================= TF32 tensor-core GEMM (BK=32, cp.async+ldmatrix)
// C[M,N] = A[M,K] @ B[N,K]^T + bias[N]; A,B already tf32-rounded.
// Block 128x256, BK=32 per stage, 256 threads (8 warps), warp 64x64.
// Smem rows = 128B (8 x 16B chunks), swizzle phys = c ^ (r&7):
//  - cp.async row stores cover full 128B lines (all 32 banks)
//  - each ldmatrix 8-row matrix gets 8 distinct chunk slots (no conflicts)
#define STG_A     16384                  // 128 rows * 128B
#define STG_B     32768                  // 256 rows * 128B
#define STG_BYTES (STG_A + STG_B)        // 49152
#define GSTAGES   3
#define GEMM_SMEM (GSTAGES * STG_BYTES)  // 147456

__global__ __launch_bounds__(256)
void gemm_tc(const float* __restrict__ A, const float* __restrict__ B,
             const float* __restrict__ bias, float* __restrict__ C,
             int M, int N, int K)
{
    extern __shared__ char smem[];
    const uint32_t sb = smem_u32(smem);

    const int tid  = threadIdx.x;
    const int lane = tid & 31;
    const int warp = tid >> 5;
    const int wm   = warp >> 2;          // 0..1
    const int wn   = warp & 3;           // 0..3
    const int g    = lane >> 2;
    const int t4   = lane & 3;

    const int bm = blockIdx.y * 128;
    const int bn = blockIdx.x * 256;

    // ---- ldmatrix per-lane bases ----
    // A: rows rA=(wm*64 + (lane&15)) + mt*16; chunk = hiA + 2*sub + 4*phase
    const int rA  = wm * 64 + (lane & 15);
    const int hiA = lane >> 4;
    const int xA  = rA & 7;              // (rA + mt*16)&7 == rA&7
    const uint32_t rowA = (uint32_t)(rA * 128);
    uint32_t offA[2][2];                 // [phase][sub]
    #pragma unroll
    for (int p = 0; p < 2; p++)
        #pragma unroll
        for (int s2 = 0; s2 < 2; s2++)
            offA[p][s2] = 16u * (uint32_t)((hiA + 2 * s2 + 4 * p) ^ xA);

    // B: rows rB=(wn*64 + (lane&7)) + nt*8; chunk = (lane>>3) + 4*phase
    const int rB  = wn * 64 + (lane & 7);
    const int cB0 = lane >> 3;
    const int xB  = rB & 7;
    const uint32_t rowB = (uint32_t)(STG_A + rB * 128);
    uint32_t offB[2];
    #pragma unroll
    for (int p = 0; p < 2; p++)
        offB[p] = 16u * (uint32_t)((cB0 + 4 * p) ^ xB);

    float4 acc[4][8];
    #pragma unroll
    for (int i = 0; i < 4; i++)
        #pragma unroll
        for (int j = 0; j < 8; j++)
            acc[i][j] = make_float4(0.f, 0.f, 0.f, 0.f);

    const int KT = K >> 5;               // 32-k stages

    // stage loader: A 1024 chunks (4/thread), B 2048 chunks (8/thread)
    #define LOADST(s, bufi) do {                                              \
        const uint32_t st_ = sb + (bufi) * STG_BYTES;                         \
        _Pragma("unroll")                                                     \
        for (int i = 0; i < 4; i++) {                                         \
            const int idx = i * 256 + tid;                                    \
            const int r = idx >> 3, kc = idx & 7;                             \
            const int sc = kc ^ (r & 7);                                      \
            cp_async16z(st_ + r * 128 + 16 * sc,                              \
                        A + (size_t)(bm + r) * K + (s) * 32 + kc * 4, true);  \
        }                                                                     \
        _Pragma("unroll")                                                     \
        for (int i = 0; i < 8; i++) {                                         \
            const int idx = i * 256 + tid;                                    \
            const int r = idx >> 3, kc = idx & 7;                             \
            const int sc = kc ^ (r & 7);                                      \
            const bool v = (bn + r) < N;                                      \
            cp_async16z(st_ + STG_A + r * 128 + 16 * sc,                      \
                        B + (size_t)(v ? (bn + r) : 0) * K + (s) * 32 + kc * 4, v); \
        }                                                                     \
        CP_COMMIT();                                                          \
    } while (0)

    LOADST(0, 0);
    LOADST(1, 1);

    int buf = 0;
    for (int kt = 0; kt < KT; kt++) {
        if (kt < KT - 1) { CP_WAIT1(); } else { CP_WAIT0(); }
        __syncthreads();
        const uint32_t st = sb + buf * STG_BYTES;

        #pragma unroll
        for (int ph = 0; ph < 2; ph++) {
            uint32_t af[4][2][4];
            #pragma unroll
            for (int mt = 0; mt < 4; mt++) {
                const uint32_t a0 = st + rowA + mt * 2048;
                ldsm_x4(af[mt][0][0], af[mt][0][1], af[mt][0][2], af[mt][0][3],
                        a0 + offA[ph][0]);
                ldsm_x4(af[mt][1][0], af[mt][1][1], af[mt][1][2], af[mt][1][3],
                        a0 + offA[ph][1]);
            }
            uint32_t bf[8][4];
            #pragma unroll
            for (int nt = 0; nt < 8; nt++)
                ldsm_x4(bf[nt][0], bf[nt][1], bf[nt][2], bf[nt][3],
                        st + rowB + nt * 1024 + offB[ph]);

            #pragma unroll
            for (int mt = 0; mt < 4; mt++)
                #pragma unroll
                for (int nt = 0; nt < 8; nt++) {
                    mma_tf32u(acc[mt][nt],
                              af[mt][0][0], af[mt][0][1], af[mt][0][2], af[mt][0][3],
                              bf[nt][0], bf[nt][1]);
                    mma_tf32u(acc[mt][nt],
                              af[mt][1][0], af[mt][1][1], af[mt][1][2], af[mt][1][3],
                              bf[nt][2], bf[nt][3]);
                }

            if (ph == 0 && kt + 2 < KT) {
                int nb = buf + 2; if (nb >= GSTAGES) nb -= GSTAGES;
                LOADST(kt + 2, nb);
            }
        }

        buf++; if (buf == GSTAGES) buf = 0;
    }
    #undef LOADST

    // -------- epilogue: bias + store --------
    #pragma unroll
    for (int mt = 0; mt < 4; mt++) {
        const int row = bm + wm * 64 + mt * 16 + g;
        #pragma unroll
        for (int nt = 0; nt < 8; nt++) {
            const int col = bn + wn * 64 + nt * 8 + 2 * t4;
            if (col < N) {
                const float bx = __ldg(bias + col), by = __ldg(bias + col + 1);
                float2 v0 = make_float2(acc[mt][nt].x + bx, acc[mt][nt].y + by);
                float2 v1 = make_float2(acc[mt][nt].z + bx, acc[mt][nt].w + by);
                *(float2*)(C + (size_t)row * N + col)       = v0;
                *(float2*)(C + (size_t)(row + 8) * N + col) = v1;
            }
        }
    }
}

// ---------------- tf32 pre-rounding kernel (single launch) --------
__global__ void cvt_all_kernel(const float4* __restrict__ hid_in,
                               const float4* __restrict__ wqkv_in,
                               const float4* __restrict__ wproj_in,
                               float4* __restrict__ hid_out,
                               float4* __restrict__ wqkv_out,
                               float4* __restrict__ wproj_out)
{
    const int n4h = (SEQ * EMBED) / 4;
    const int n4q = (QKVD * EMBED) / 4;
    const int n4p = (EMBED * NECK) / 4;
    int i = blockIdx.x * blockDim.x + threadIdx.x;
    const float4* in;
    float4* out;
    if (i < n4h)            { in = hid_in + i;                 out = hid_out + i; }
    else if (i < n4h + n4q) { in = wqkv_in + (i - n4h);        out = wqkv_out + (i - n4h); }
    else if (i < n4h + n4q + n4p) { in = wproj_in + (i - n4h - n4q); out = wproj_out + (i - n4h - n4q); }
    else return;
    float4 v = *in;
    v.x = to_tf32(v.x); v.y = to_tf32(v.y);
    v.z = to_tf32(v.z); v.w = to_tf32(v.w);
    *out = v;
}

// ---------------- RoPE + tf32 round (8 rows/block, shared trig) ---
__global__ __launch_bounds__(256)
void rope_round_kernel(float* __restrict__ qkv,
                       const float* __restrict__ freqs)   // [T,40]
{
    const int row0 = blockIdx.x * 8;     // 8 consecutive rows share t
    const int t    = row0 >> 8;
    float* rbase = qkv + (size_t)row0 * QKVD;

    __shared__ float cs[40], sn[40];
    if (threadIdx.x < 40) {
        const float f = freqs[t * 40 + threadIdx.x];
        cs[threadIdx.x] = cosf(f);
        sn[threadIdx.x] = sinf(f);
    }
    __syncthreads();

    // Q/K rotations: 8 rows * 320 pair-items
    for (int i = threadIdx.x; i < 8 * 320; i += 256) {
        const int rl  = i / 320;
        const int it  = i % 320;
        const int sec = it / 160;        // 0=Q, 1=K
        const int hh  = (it % 160) / 40;
        const int j   = it % 40;
        float* p = rbase + (size_t)rl * QKVD + sec * NECK + hh * HDIM;
        const float x1 = p[j], x2 = p[j + 40];
        p[j]      = to_tf32(x1 * cs[j] - x2 * sn[j]);
        p[j + 40] = to_tf32(x2 * cs[j] + x1 * sn[j]);
    }
    // V rounding: 8 rows * 320 floats
    for (int i = threadIdx.x; i < 8 * NECK; i += 256) {
        const int rl = i / NECK, j = i % NECK;
        float* p = rbase + (size_t)rl * QKVD + 2 * NECK;
        p[j] = to_tf32(p[j]);
    }
}

// ---------------- Tensor-core flash attention (R7, unchanged) -----
#define ATT_SMEM ((20480 + 20480 + 8192) * 4)

#define PADDR(r, ck) ((((ck) >> 4) << 8) + ((r) << 4) + \
                      ((((ck) & 3) ^ ((r) & 3)) << 2) + (((ck) >> 2) & 3))

__global__ __launch_bounds__(256)
void attn_tc_kernel(const float* __restrict__ qkv,
                    float* __restrict__ attout)
{
    extern __shared__ float sh[];
    float* Ks = sh;
    float* Vs = sh + 20480;

    const int s    = blockIdx.x;
    const int h    = blockIdx.y;
    const int tid  = threadIdx.x;
    const int lane = tid & 31;
    const int w    = tid >> 5;
    const int g    = lane >> 2;
    const int t4   = lane & 3;
    const int hb   = h * HDIM;

    for (int i = tid; i < TC * HDIM; i += 256) {
        const int t = i / HDIM, d = i % HDIM;
        const float v = qkv[(size_t)(t * S1C + s) * QKVD + NECK + hb + d];
        Ks[t * 80 + ((d >> 4) << 4) + (((d & 3) ^ (t & 3)) << 2) + ((d >> 2) & 3)] = v;
    }
    for (int i = tid; i < TC * HDIM; i += 256) {
        const int t = i / HDIM, d = i % HDIM;
        const float v = qkv[(size_t)(t * S1C + s) * QKVD + 2 * NECK + hb + d];
        Vs[(t >> 4) * 1280 + (d << 4) + (((t & 3) ^ (d & 3)) << 2) + ((t >> 2) & 3)] = v;
    }
    __syncthreads();

    float* Pw = sh + 40960 + w * 1024;
    const float scale = 0.111803398874989484f;   // 1/sqrt(80)
    const int swg = ((t4 ^ (g & 3)) << 2);

    #pragma unroll
    for (int rg = 0; rg < 2; rg++) {
        const int R0 = w * 32 + rg * 16;

        float4 qa[5], qb[5];
        {
            const float* p0 = qkv + (size_t)((R0 + g) * S1C + s) * QKVD + hb + t4;
            const float* p1 = qkv + (size_t)((R0 + g + 8) * S1C + s) * QKVD + hb + t4;
            #pragma unroll
            for (int b = 0; b < 5; b++) {
                qa[b] = make_float4(p0[b*16], p0[b*16+4], p0[b*16+8], p0[b*16+12]);
                qb[b] = make_float4(p1[b*16], p1[b*16+4], p1[b*16+8], p1[b*16+12]);
            }
        }

        float m0 = -1e30f, m1 = -1e30f, l0 = 0.f, l1 = 0.f;
        float4 o[10];
        #pragma unroll
        for (int dt = 0; dt < 10; dt++) o[dt] = make_float4(0.f, 0.f, 0.f, 0.f);

        for (int c = 0; c < 4; c++) {
            float4 sacc[8];
            #pragma unroll
            for (int nt = 0; nt < 8; nt++) sacc[nt] = make_float4(0.f, 0.f, 0.f, 0.f);
            #pragma unroll
            for (int nt = 0; nt < 8; nt++) {
                const int krow = c * 64 + nt * 8 + g;
                const float* pb = Ks + krow * 80 + swg;
                #pragma unroll
                for (int b = 0; b < 5; b++) {
                    const float4 fb = *(const float4*)(pb + b * 16);
                    mma_tf32(sacc[nt], qa[b].x, qb[b].x, qa[b].y, qb[b].y, fb.x, fb.y);
                    mma_tf32(sacc[nt], qa[b].z, qb[b].z, qa[b].w, qb[b].w, fb.z, fb.w);
                }
            }

            float mx0 = -1e30f, mx1 = -1e30f;
            #pragma unroll
            for (int nt = 0; nt < 8; nt++) {
                sacc[nt].x *= scale; sacc[nt].y *= scale;
                sacc[nt].z *= scale; sacc[nt].w *= scale;
                mx0 = fmaxf(mx0, fmaxf(sacc[nt].x, sacc[nt].y));
                mx1 = fmaxf(mx1, fmaxf(sacc[nt].z, sacc[nt].w));
            }
            mx0 = fmaxf(mx0, __shfl_xor_sync(0xffffffffu, mx0, 1));
            mx0 = fmaxf(mx0, __shfl_xor_sync(0xffffffffu, mx0, 2));
            mx1 = fmaxf(mx1, __shfl_xor_sync(0xffffffffu, mx1, 1));
            mx1 = fmaxf(mx1, __shfl_xor_sync(0xffffffffu, mx1, 2));

            const float mn0 = fmaxf(m0, mx0), mn1 = fmaxf(m1, mx1);
            const float cor0 = __expf(m0 - mn0), cor1 = __expf(m1 - mn1);

            float s0 = 0.f, s1 = 0.f;
            #pragma unroll
            for (int nt = 0; nt < 8; nt++) {
                sacc[nt].x = __expf(sacc[nt].x - mn0); s0 += sacc[nt].x;
                sacc[nt].y = __expf(sacc[nt].y - mn0); s0 += sacc[nt].y;
                sacc[nt].z = __expf(sacc[nt].z - mn1); s1 += sacc[nt].z;
                sacc[nt].w = __expf(sacc[nt].w - mn1); s1 += sacc[nt].w;
            }
            s0 += __shfl_xor_sync(0xffffffffu, s0, 1);
            s0 += __shfl_xor_sync(0xffffffffu, s0, 2);
            s1 += __shfl_xor_sync(0xffffffffu, s1, 1);
            s1 += __shfl_xor_sync(0xffffffffu, s1, 2);

            l0 = l0 * cor0 + s0;  l1 = l1 * cor1 + s1;
            m0 = mn0;             m1 = mn1;

            #pragma unroll
            for (int dt = 0; dt < 10; dt++) {
                o[dt].x *= cor0; o[dt].y *= cor0;
                o[dt].z *= cor1; o[dt].w *= cor1;
            }

            __syncwarp();
            #pragma unroll
            for (int nt = 0; nt < 8; nt++) {
                const int ck0 = nt * 8 + 2 * t4;
                Pw[PADDR(g,     ck0    )] = to_tf32(sacc[nt].x);
                Pw[PADDR(g,     ck0 + 1)] = to_tf32(sacc[nt].y);
                Pw[PADDR(g + 8, ck0    )] = to_tf32(sacc[nt].z);
                Pw[PADDR(g + 8, ck0 + 1)] = to_tf32(sacc[nt].w);
            }
            __syncwarp();

            float4 pa[4], pc[4];
            #pragma unroll
            for (int kb = 0; kb < 4; kb++) {
                const float* pp = Pw + kb * 256 + g * 16 + swg;
                pa[kb] = *(const float4*)(pp);
                pc[kb] = *(const float4*)(pp + 128);
            }
            #pragma unroll
            for (int dt = 0; dt < 10; dt++) {
                const int drow = dt * 8 + g;
                const float* pv = Vs + (c * 4) * 1280 + drow * 16 + swg;
                #pragma unroll
                for (int kb = 0; kb < 4; kb++) {
                    const float4 fv = *(const float4*)(pv + kb * 1280);
                    mma_tf32(o[dt], pa[kb].x, pc[kb].x, pa[kb].y, pc[kb].y, fv.x, fv.y);
                    mma_tf32(o[dt], pa[kb].z, pc[kb].z, pa[kb].w, pc[kb].w, fv.z, fv.w);
                }
            }
        }

        const float il0 = 1.f / l0, il1 = 1.f / l1;
        const int col = hb + 2 * t4;
        #pragma unroll
        for (int dt = 0; dt < 10; dt++) {
            float2 v0 = make_float2(to_tf32(o[dt].x * il0), to_tf32(o[dt].y * il0));
            float2 v1 = make_float2(to_tf32(o[dt].z * il1), to_tf32(o[dt].w * il1));
            *(float2*)(attout + (size_t)(s * TC + R0 + g)     * NECK + col + dt * 8) = v0;
            *(float2*)(attout + (size_t)(s * TC + R0 + g + 8) * NECK + col + dt * 8) = v1;
        }
    }
}

// ---------------- Launch -------------------------------------------
extern "C" void kernel_launch(void* const* d_in, const int* in_sizes, int n_in,
                              void* d_out, int out_size)
{
    const float* hidden = (const float*)d_in[0];
    const float* freqs  = (const float*)d_in[2];
    const float* w_qkv  = (const float*)d_in[3];
    const float* b_qkv  = (const float*)d_in[4];
    const float* w_proj = (const float*)d_in[5];
    const float* b_proj = (const float*)d_in[6];
    float* out = (float*)d_out;

    float *qkv_p, *att_p, *hid_p, *wqkv_p, *wproj_p;
    cudaGetSymbolAddress((void**)&qkv_p,   g_qkv);
    cudaGetSymbolAddress((void**)&att_p,   g_att);
    cudaGetSymbolAddress((void**)&hid_p,   g_hid);
    cudaGetSymbolAddress((void**)&wqkv_p,  g_wqkv);
    cudaGetSymbolAddress((void**)&wproj_p, g_wproj);

    // 0) tf32-round inputs once (single fused launch)
    {
        const int n4 = (SEQ * EMBED + QKVD * EMBED + EMBED * NECK) / 4;
        cvt_all_kernel<<<(n4 + 255) / 256, 256>>>(
            (const float4*)hidden, (const float4*)w_qkv, (const float4*)w_proj,
            (float4*)hid_p, (float4*)wqkv_p, (float4*)wproj_p);
    }

    // 1) QKV GEMM: [65536,960] = hid @ w_qkv^T + b_qkv   (K=1280)
    {
        cudaFuncSetAttribute(gemm_tc,
                             cudaFuncAttributeMaxDynamicSharedMemorySize, GEMM_SMEM);
        dim3 grid((QKVD + 255) / 256, SEQ / 128);   // 4 x 512
        gemm_tc<<<grid, 256, GEMM_SMEM>>>(hid_p, wqkv_p, b_qkv, qkv_p,
                                          SEQ, QKVD, EMBED);
    }

    // 1.5) RoPE + tf32 round (in place on g_qkv)
    rope_round_kernel<<<SEQ / 8, 256>>>(qkv_p, freqs);

    // 2) Tensor-core attention -> g_att (tf32)
    {
        cudaFuncSetAttribute(attn_tc_kernel,
                             cudaFuncAttributeMaxDynamicSharedMemorySize, ATT_SMEM);
        dim3 grid(S1C, NHEAD);
        attn_tc_kernel<<<grid, 256, ATT_SMEM>>>(qkv_p, att_p);
    }

    // 3) Proj GEMM: out[65536,1280] = att @ w_proj^T + b_proj  (K=320)
    {
        dim3 grid(EMBED / 256, SEQ / 128);          // 5 x 512
        gemm_tc<<<grid, 256, GEMM_SMEM>>>(att_p, wproj_p, b_proj, out,
                                          SEQ, EMBED, NECK);
    }
}